// round 8
// baseline (speedup 1.0000x reference)
#include <cuda_runtime.h>
#include <cstdint>
#include <math.h>

#define T_TOK 16384
#define DIMN  1024
#define HIDN  2048
#define NE    8
#define NA    (2*T_TOK)

#define BK    16
#define PADA  20    // row stride (floats) for A / NT-B tiles
#define PADB  136   // row stride (floats) for ffn2 B tile [16][128]
#define NSTG  3

// ============================ helpers ============================
#define CP_ASYNC16(dst, src) asm volatile("cp.async.cg.shared.global [%0], [%1], 16;" :: "r"(dst), "l"(src))
#define CP_COMMIT()          asm volatile("cp.async.commit_group;" ::: "memory")
#define CP_WAIT(n)           asm volatile("cp.async.wait_group %0;" :: "n"(n) : "memory")

__device__ __forceinline__ uint32_t smem_u32(const void* p) {
    uint32_t a;
    asm("{ .reg .u64 t; cvta.to.shared.u64 t, %1; cvt.u32.u64 %0, t; }" : "=r"(a) : "l"(p));
    return a;
}
__device__ __forceinline__ float tf32r(float x) {
    uint32_t u; asm("cvt.rna.tf32.f32 %0, %1;" : "=r"(u) : "f"(x)); return __uint_as_float(u);
}
__device__ __forceinline__ void mma_tf32(float* c, const uint32_t* a, const uint32_t* b) {
    asm volatile(
        "mma.sync.aligned.m16n8k8.row.col.f32.tf32.tf32.f32 "
        "{%0,%1,%2,%3}, {%4,%5,%6,%7}, {%8,%9}, {%0,%1,%2,%3};"
        : "+f"(c[0]), "+f"(c[1]), "+f"(c[2]), "+f"(c[3])
        : "r"(a[0]), "r"(a[1]), "r"(a[2]), "r"(a[3]), "r"(b[0]), "r"(b[1]));
}

// ============================ device scratch ============================
__device__ int   g_count[NE];
__device__ int   g_count2[NE];
__device__ int   g_off[NE];
__device__ int   g_choice[T_TOK * 2];
__device__ float g_cw[T_TOK * 2];
__device__ int   g_tokOf[NA];
__device__ float g_wt[NA];
__device__ int   g_slot[T_TOK * 2];
__device__ float g_Xg[(size_t)NA * DIMN];          // gathered tokens, tf32-rounded
__device__ float g_Ht[(size_t)NA * HIDN];          // hidden, tf32-rounded
__device__ float g_P [(size_t)NA * DIMN];          // per-assignment partials
__device__ float g_w1t[(size_t)NE * HIDN * DIMN];  // tf32-rounded
__device__ float g_w3t[(size_t)NE * HIDN * DIMN];
__device__ float g_w2r[(size_t)NE * HIDN * DIMN];  // tf32-rounded (same layout as w2)

// ============================ small kernels ============================
__global__ void reset_kernel() {
    if (threadIdx.x < NE) { g_count[threadIdx.x] = 0; g_count2[threadIdx.x] = 0; }
}

__global__ void gate_kernel(const float* __restrict__ x, const float* __restrict__ wg) {
    int warp = threadIdx.x >> 5, lane = threadIdx.x & 31;
    int t = blockIdx.x * 8 + warp;
    if (t >= T_TOK) return;
    float acc[NE];
#pragma unroll
    for (int e = 0; e < NE; e++) acc[e] = 0.f;
    const float* xr = x + (size_t)t * DIMN;
    for (int d = lane; d < DIMN; d += 32) {
        float xv = xr[d];
#pragma unroll
        for (int e = 0; e < NE; e++) acc[e] += xv * wg[d * NE + e];
    }
#pragma unroll
    for (int e = 0; e < NE; e++)
#pragma unroll
        for (int o = 16; o > 0; o >>= 1) acc[e] += __shfl_xor_sync(0xffffffffu, acc[e], o);
    if (lane == 0) {
        int i0 = 0; float l0 = acc[0];
#pragma unroll
        for (int e = 1; e < NE; e++) if (acc[e] > l0) { l0 = acc[e]; i0 = e; }
        int i1 = -1; float l1 = -3.0e38f;
#pragma unroll
        for (int e = 0; e < NE; e++) if (e != i0 && acc[e] > l1) { l1 = acc[e]; i1 = e; }
        float w0 = 1.f / (1.f + expf(l1 - l0));
        g_choice[2 * t] = i0;  g_choice[2 * t + 1] = i1;
        g_cw[2 * t] = w0;      g_cw[2 * t + 1] = 1.f - w0;
        atomicAdd(&g_count[i0], 1);
        atomicAdd(&g_count[i1], 1);
    }
}

__global__ void scan_kernel() {
    if (threadIdx.x == 0) {
        int off = 0;
        for (int e = 0; e < NE; e++) { g_off[e] = off; off += g_count[e]; }
    }
}

__global__ void build_kernel() {
    int t = blockIdx.x * blockDim.x + threadIdx.x;
    if (t >= T_TOK) return;
#pragma unroll
    for (int j = 0; j < 2; j++) {
        int e = g_choice[2 * t + j];
        int p = atomicAdd(&g_count2[e], 1);
        int s = g_off[e] + p;
        g_tokOf[s] = t;
        g_wt[s] = g_cw[2 * t + j];
        g_slot[2 * t + j] = s;
    }
}

__global__ void gather_kernel(const float* __restrict__ x) {
    size_t idx = (size_t)blockIdx.x * blockDim.x + threadIdx.x;
    if (idx >= (size_t)NA * (DIMN / 4)) return;
    int row = (int)(idx / (DIMN / 4));
    int c4 = (int)(idx % (DIMN / 4)) * 4;
    int tok = g_tokOf[row];
    float4 v = *reinterpret_cast<const float4*>(&x[(size_t)tok * DIMN + c4]);
    v.x = tf32r(v.x); v.y = tf32r(v.y); v.z = tf32r(v.z); v.w = tf32r(v.w);
    *reinterpret_cast<float4*>(&g_Xg[(size_t)row * DIMN + c4]) = v;
}

__global__ void convw_kernel(const float* __restrict__ w1, const float* __restrict__ w2,
                             const float* __restrict__ w3) {
    size_t idx = (size_t)blockIdx.x * blockDim.x + threadIdx.x;
    if (idx >= (size_t)NE * HIDN * DIMN / 4) return;
    size_t o = idx * 4;
    float4 a = *reinterpret_cast<const float4*>(&w1[o]);
    a.x = tf32r(a.x); a.y = tf32r(a.y); a.z = tf32r(a.z); a.w = tf32r(a.w);
    *reinterpret_cast<float4*>(&g_w1t[o]) = a;
    float4 b = *reinterpret_cast<const float4*>(&w3[o]);
    b.x = tf32r(b.x); b.y = tf32r(b.y); b.z = tf32r(b.z); b.w = tf32r(b.w);
    *reinterpret_cast<float4*>(&g_w3t[o]) = b;
    float4 c = *reinterpret_cast<const float4*>(&w2[o]);
    c.x = tf32r(c.x); c.y = tf32r(c.y); c.z = tf32r(c.z); c.w = tf32r(c.w);
    *reinterpret_cast<float4*>(&g_w2r[o]) = c;
}

// ============================ ffn1: H = silu(Xg W1^T) * (Xg W3^T) ============================
// BM=128 BN=64 BK=16. 128 threads, 4 warps as 2(m) x 2(n); warp tile 64x32 (dual output).
__global__ void __launch_bounds__(128, 2) ffn1_kernel() {
    int e = blockIdx.z;
    int cnt = g_count[e];
    int mb = blockIdx.y;
    if (mb * 128 >= cnt) return;
    int base = g_off[e] + mb * 128;
    int n0 = blockIdx.x * 64;

    extern __shared__ float smem[];
    float* As  = smem;                       // [NSTG][128*PADA]
    float* B1s = As  + NSTG * 128 * PADA;    // [NSTG][64*PADA]
    float* B3s = B1s + NSTG * 64 * PADA;     // [NSTG][64*PADA]
    const int A_STG = 128 * PADA, B_STG = 64 * PADA;

    int tid = threadIdx.x, warp = tid >> 5, lane = tid & 31;
    int wm = warp >> 1, wn = warp & 1;

    // A loader: one 16-float row slice per thread
    int arow = base + tid; if (arow >= NA) arow = NA - 1;
    const float* srcA0 = g_Xg + (size_t)arow * DIMN;
    uint32_t dstA0 = smem_u32(&As[tid * PADA]);

    // B loader: threads 0-63 -> B1 rows, 64-127 -> B3 rows
    int brow = tid & 63;
    int bmat = tid >> 6;
    const float* srcB0 = (bmat ? g_w3t : g_w1t) + ((size_t)e * HIDN + n0 + brow) * DIMN;
    uint32_t dstB0 = smem_u32((bmat ? B3s : B1s) + brow * PADA);

    float acc1[4][4][4], acc3[4][4][4];
#pragma unroll
    for (int i = 0; i < 4; i++)
#pragma unroll
        for (int j = 0; j < 4; j++)
#pragma unroll
            for (int v = 0; v < 4; v++) { acc1[i][j][v] = 0.f; acc3[i][j][v] = 0.f; }

    auto issue = [&](int s, int kc) {
        uint32_t aoff = (uint32_t)(s * A_STG * 4);
        uint32_t boff = (uint32_t)(s * B_STG * 4);
        const float* sa = srcA0 + kc * BK;
        CP_ASYNC16(dstA0 + aoff,      sa);
        CP_ASYNC16(dstA0 + aoff + 16, sa + 4);
        CP_ASYNC16(dstA0 + aoff + 32, sa + 8);
        CP_ASYNC16(dstA0 + aoff + 48, sa + 12);
        const float* sb = srcB0 + kc * BK;
        CP_ASYNC16(dstB0 + boff,      sb);
        CP_ASYNC16(dstB0 + boff + 16, sb + 4);
        CP_ASYNC16(dstB0 + boff + 32, sb + 8);
        CP_ASYNC16(dstB0 + boff + 48, sb + 12);
        CP_COMMIT();
    };

    const int KT = DIMN / BK;   // 64
    issue(0, 0); issue(1, 1);

    int stg = 0;
    for (int kt = 0; kt < KT; kt++) {
        CP_WAIT(1);
        __syncthreads();
        if (kt + 2 < KT) {
            int s = stg + 2; if (s >= NSTG) s -= NSTG;
            issue(s, kt + 2);
        }

        const float* A  = As  + stg * A_STG;
        const float* B1 = B1s + stg * B_STG;
        const float* B3 = B3s + stg * B_STG;
#pragma unroll
        for (int kk = 0; kk < 2; kk++) {
            int c = kk * 8 + (lane & 3);
            uint32_t a[4][4];
#pragma unroll
            for (int i = 0; i < 4; i++) {
                int r = wm * 64 + i * 16 + (lane >> 2);
                a[i][0] = __float_as_uint(A[r * PADA + c]);
                a[i][1] = __float_as_uint(A[(r + 8) * PADA + c]);
                a[i][2] = __float_as_uint(A[r * PADA + c + 4]);
                a[i][3] = __float_as_uint(A[(r + 8) * PADA + c + 4]);
            }
            uint32_t b1[4][2], b3[4][2];
#pragma unroll
            for (int j = 0; j < 4; j++) {
                int n = wn * 32 + j * 8 + (lane >> 2);
                b1[j][0] = __float_as_uint(B1[n * PADA + c]);
                b1[j][1] = __float_as_uint(B1[n * PADA + c + 4]);
                b3[j][0] = __float_as_uint(B3[n * PADA + c]);
                b3[j][1] = __float_as_uint(B3[n * PADA + c + 4]);
            }
#pragma unroll
            for (int i = 0; i < 4; i++)
#pragma unroll
                for (int j = 0; j < 4; j++) {
                    mma_tf32(acc1[i][j], a[i], b1[j]);
                    mma_tf32(acc3[i][j], a[i], b3[j]);
                }
        }
        if (++stg >= NSTG) stg = 0;
    }
    CP_WAIT(0);

    // epilogue: h = silu(z1)*z3, tf32-round, store
#pragma unroll
    for (int i = 0; i < 4; i++) {
#pragma unroll
        for (int half = 0; half < 2; half++) {
            int rloc = wm * 64 + i * 16 + (lane >> 2) + half * 8;
            if (mb * 128 + rloc < cnt) {
                float* hrow = g_Ht + (size_t)(base + rloc) * HIDN + n0;
#pragma unroll
                for (int j = 0; j < 4; j++) {
                    int cl = wn * 32 + j * 8 + (lane & 3) * 2;
                    float z0 = acc1[i][j][half * 2 + 0];
                    float z1 = acc1[i][j][half * 2 + 1];
                    float h0 = tf32r(z0 / (1.f + __expf(-z0)) * acc3[i][j][half * 2 + 0]);
                    float h1 = tf32r(z1 / (1.f + __expf(-z1)) * acc3[i][j][half * 2 + 1]);
                    *reinterpret_cast<float2*>(&hrow[cl]) = make_float2(h0, h1);
                }
            }
        }
    }
}

// ============================ ffn2: P = H W2 ============================
// BM=128 BN=128 BK=16. 128 threads, 4 warps as 2(m) x 2(n); warp tile 64x64.
__global__ void __launch_bounds__(128, 2) ffn2_kernel() {
    int e = blockIdx.z;
    int cnt = g_count[e];
    int mb = blockIdx.y;
    if (mb * 128 >= cnt) return;
    int base = g_off[e] + mb * 128;
    int n0 = blockIdx.x * 128;

    extern __shared__ float smem[];
    float* As = smem;                        // [NSTG][128*PADA]
    float* Bs = As + NSTG * 128 * PADA;      // [NSTG][16*PADB]
    const int A_STG = 128 * PADA, B_STG = 16 * PADB;

    int tid = threadIdx.x, warp = tid >> 5, lane = tid & 31;
    int wm = warp >> 1, wn = warp & 1;

    int arow = base + tid; if (arow >= NA) arow = NA - 1;
    const float* srcA0 = g_Ht + (size_t)arow * HIDN;
    uint32_t dstA0 = smem_u32(&As[tid * PADA]);

    // B loader: 16 rows x 128 floats; thread -> row tid>>3, col (tid&7)*16
    int brow = tid >> 3;
    int bcol = (tid & 7) * 16;
    const float* srcB0 = g_w2r + ((size_t)e * HIDN + brow) * DIMN + n0 + bcol;
    uint32_t dstB0 = smem_u32(&Bs[brow * PADB + bcol]);

    float acc[4][8][4];
#pragma unroll
    for (int i = 0; i < 4; i++)
#pragma unroll
        for (int j = 0; j < 8; j++)
#pragma unroll
            for (int v = 0; v < 4; v++) acc[i][j][v] = 0.f;

    auto issue = [&](int s, int kc) {
        uint32_t aoff = (uint32_t)(s * A_STG * 4);
        uint32_t boff = (uint32_t)(s * B_STG * 4);
        const float* sa = srcA0 + kc * BK;
        CP_ASYNC16(dstA0 + aoff,      sa);
        CP_ASYNC16(dstA0 + aoff + 16, sa + 4);
        CP_ASYNC16(dstA0 + aoff + 32, sa + 8);
        CP_ASYNC16(dstA0 + aoff + 48, sa + 12);
        const float* sb = srcB0 + (size_t)kc * BK * DIMN;
        CP_ASYNC16(dstB0 + boff,      sb);
        CP_ASYNC16(dstB0 + boff + 16, sb + 4);
        CP_ASYNC16(dstB0 + boff + 32, sb + 8);
        CP_ASYNC16(dstB0 + boff + 48, sb + 12);
        CP_COMMIT();
    };

    const int KT = HIDN / BK;   // 128
    issue(0, 0); issue(1, 1);

    int stg = 0;
    for (int kt = 0; kt < KT; kt++) {
        CP_WAIT(1);
        __syncthreads();
        if (kt + 2 < KT) {
            int s = stg + 2; if (s >= NSTG) s -= NSTG;
            issue(s, kt + 2);
        }

        const float* A = As + stg * A_STG;
        const float* B = Bs + stg * B_STG;
#pragma unroll
        for (int kk = 0; kk < 2; kk++) {
            int c = kk * 8 + (lane & 3);
            uint32_t a[4][4];
#pragma unroll
            for (int i = 0; i < 4; i++) {
                int r = wm * 64 + i * 16 + (lane >> 2);
                a[i][0] = __float_as_uint(A[r * PADA + c]);
                a[i][1] = __float_as_uint(A[(r + 8) * PADA + c]);
                a[i][2] = __float_as_uint(A[r * PADA + c + 4]);
                a[i][3] = __float_as_uint(A[(r + 8) * PADA + c + 4]);
            }
            uint32_t b[8][2];
#pragma unroll
            for (int j = 0; j < 8; j++) {
                int n = wn * 64 + j * 8 + (lane >> 2);
                b[j][0] = __float_as_uint(B[c * PADB + n]);
                b[j][1] = __float_as_uint(B[(c + 4) * PADB + n]);
            }
#pragma unroll
            for (int i = 0; i < 4; i++)
#pragma unroll
                for (int j = 0; j < 8; j++)
                    mma_tf32(acc[i][j], a[i], b[j]);
        }
        if (++stg >= NSTG) stg = 0;
    }
    CP_WAIT(0);

#pragma unroll
    for (int i = 0; i < 4; i++) {
#pragma unroll
        for (int half = 0; half < 2; half++) {
            int rloc = wm * 64 + i * 16 + (lane >> 2) + half * 8;
            if (mb * 128 + rloc < cnt) {
                float* prow = g_P + (size_t)(base + rloc) * DIMN + n0;
#pragma unroll
                for (int j = 0; j < 8; j++) {
                    int cl = wn * 64 + j * 8 + (lane & 3) * 2;
                    *reinterpret_cast<float2*>(&prow[cl]) =
                        make_float2(acc[i][j][half * 2 + 0], acc[i][j][half * 2 + 1]);
                }
            }
        }
    }
}

// ============================ combine ============================
__global__ void combine_kernel(float* __restrict__ y) {
    size_t idx = (size_t)blockIdx.x * blockDim.x + threadIdx.x;
    if (idx >= (size_t)T_TOK * DIMN / 4) return;
    int t = (int)(idx / (DIMN / 4));
    int d4 = (int)(idx % (DIMN / 4)) * 4;
    int s0 = g_slot[2 * t], s1 = g_slot[2 * t + 1];
    float w0 = g_wt[s0], w1 = g_wt[s1];
    float4 p0 = *reinterpret_cast<const float4*>(&g_P[(size_t)s0 * DIMN + d4]);
    float4 p1 = *reinterpret_cast<const float4*>(&g_P[(size_t)s1 * DIMN + d4]);
    float4 r;
    r.x = w0 * p0.x + w1 * p1.x;
    r.y = w0 * p0.y + w1 * p1.y;
    r.z = w0 * p0.z + w1 * p1.z;
    r.w = w0 * p0.w + w1 * p1.w;
    *reinterpret_cast<float4*>(&y[(size_t)t * DIMN + d4]) = r;
}

// ============================ launch ============================
extern "C" void kernel_launch(void* const* d_in, const int* in_sizes, int n_in,
                              void* d_out, int out_size) {
    const float* x  = (const float*)d_in[0];
    const float* wg = (const float*)d_in[1];
    const float* w1 = (const float*)d_in[2];
    const float* w2 = (const float*)d_in[3];
    const float* w3 = (const float*)d_in[4];
    float* y = (float*)d_out;

    const int smem1 = NSTG * (128 + 64 + 64) * PADA * 4;      // 61440
    const int smem2 = NSTG * (128 * PADA + 16 * PADB) * 4;    // 56832
    cudaFuncSetAttribute(ffn1_kernel, cudaFuncAttributeMaxDynamicSharedMemorySize, smem1);
    cudaFuncSetAttribute(ffn2_kernel, cudaFuncAttributeMaxDynamicSharedMemorySize, smem2);

    reset_kernel<<<1, 32>>>();
    gate_kernel<<<T_TOK / 8, 256>>>(x, wg);
    scan_kernel<<<1, 32>>>();
    build_kernel<<<T_TOK / 256, 256>>>();
    gather_kernel<<<(int)(((size_t)NA * (DIMN / 4) + 255) / 256), 256>>>(x);
    convw_kernel<<<(int)(((size_t)NE * HIDN * DIMN / 4 + 255) / 256), 256>>>(w1, w2, w3);
    ffn1_kernel<<<dim3(HIDN / 64, 128, NE), 128, smem1>>>();
    ffn2_kernel<<<dim3(DIMN / 128, 128, NE), 128, smem2>>>();
    combine_kernel<<<(T_TOK * DIMN / 4 + 255) / 256, 256>>>(y);
}

// round 9
// speedup vs baseline: 2.2097x; 2.2097x over previous
#include <cuda_runtime.h>
#include <cuda_fp16.h>
#include <cstdint>
#include <math.h>

#define T_TOK 16384
#define DIMN  1024
#define HIDN  2048
#define NE    8
#define NA    (2*T_TOK)

#define BKF   32     // fp16 elements of K per stage
#define PADU  20     // smem row stride in u32 (16 payload + 4 pad)
#define NSTG  3

// ============================ helpers ============================
#define CP_ASYNC16(dst, src) asm volatile("cp.async.cg.shared.global [%0], [%1], 16;" :: "r"(dst), "l"(src))
#define CP_COMMIT()          asm volatile("cp.async.commit_group;" ::: "memory")
#define CP_WAIT(n)           asm volatile("cp.async.wait_group %0;" :: "n"(n) : "memory")

__device__ __forceinline__ uint32_t smem_u32(const void* p) {
    uint32_t a;
    asm("{ .reg .u64 t; cvta.to.shared.u64 t, %1; cvt.u32.u64 %0, t; }" : "=r"(a) : "l"(p));
    return a;
}
__device__ __forceinline__ uint32_t pack_h2(float lo, float hi) {
    __half2 h = __floats2half2_rn(lo, hi);
    return *reinterpret_cast<uint32_t*>(&h);
}
// fp16 MMA m16n8k16, fp32 accumulate
__device__ __forceinline__ void mma_f16(float* c, const uint32_t* a, const uint32_t* b) {
    asm volatile(
        "mma.sync.aligned.m16n8k16.row.col.f32.f16.f16.f32 "
        "{%0,%1,%2,%3}, {%4,%5,%6,%7}, {%8,%9}, {%0,%1,%2,%3};"
        : "+f"(c[0]), "+f"(c[1]), "+f"(c[2]), "+f"(c[3])
        : "r"(a[0]), "r"(a[1]), "r"(a[2]), "r"(a[3]), "r"(b[0]), "r"(b[1]));
}

// ============================ device scratch ============================
__device__ int      g_count[NE];
__device__ int      g_count2[NE];
__device__ int      g_off[NE];
__device__ int      g_choice[T_TOK * 2];
__device__ float    g_cw[T_TOK * 2];
__device__ int      g_tokOf[NA];
__device__ float    g_wt[NA];
__device__ int      g_slot[T_TOK * 2];
__device__ uint32_t g_Xh [(size_t)NA * DIMN / 2];          // gathered tokens, fp16 pairs
__device__ uint32_t g_Hh [(size_t)NA * HIDN / 2];          // hidden, fp16 pairs
__device__ float    g_P  [(size_t)NA * DIMN];              // per-assignment partials (fp32)
__device__ uint32_t g_w1h[(size_t)NE * HIDN * DIMN / 2];   // fp16 pairs [e][n][k/2]
__device__ uint32_t g_w3h[(size_t)NE * HIDN * DIMN / 2];
__device__ uint32_t g_w2h[(size_t)NE * DIMN * HIDN / 2];   // TRANSPOSED fp16 pairs [e][n(dim)][k(hid)/2]

// ============================ small kernels ============================
__global__ void reset_kernel() {
    if (threadIdx.x < NE) { g_count[threadIdx.x] = 0; g_count2[threadIdx.x] = 0; }
}

__global__ void gate_kernel(const float* __restrict__ x, const float* __restrict__ wg) {
    int warp = threadIdx.x >> 5, lane = threadIdx.x & 31;
    int t = blockIdx.x * 8 + warp;
    if (t >= T_TOK) return;
    float acc[NE];
#pragma unroll
    for (int e = 0; e < NE; e++) acc[e] = 0.f;
    const float* xr = x + (size_t)t * DIMN;
    for (int d = lane; d < DIMN; d += 32) {
        float xv = xr[d];
#pragma unroll
        for (int e = 0; e < NE; e++) acc[e] += xv * wg[d * NE + e];
    }
#pragma unroll
    for (int e = 0; e < NE; e++)
#pragma unroll
        for (int o = 16; o > 0; o >>= 1) acc[e] += __shfl_xor_sync(0xffffffffu, acc[e], o);
    if (lane == 0) {
        int i0 = 0; float l0 = acc[0];
#pragma unroll
        for (int e = 1; e < NE; e++) if (acc[e] > l0) { l0 = acc[e]; i0 = e; }
        int i1 = -1; float l1 = -3.0e38f;
#pragma unroll
        for (int e = 0; e < NE; e++) if (e != i0 && acc[e] > l1) { l1 = acc[e]; i1 = e; }
        float w0 = 1.f / (1.f + expf(l1 - l0));
        g_choice[2 * t] = i0;  g_choice[2 * t + 1] = i1;
        g_cw[2 * t] = w0;      g_cw[2 * t + 1] = 1.f - w0;
        atomicAdd(&g_count[i0], 1);
        atomicAdd(&g_count[i1], 1);
    }
}

__global__ void scan_kernel() {
    if (threadIdx.x == 0) {
        int off = 0;
        for (int e = 0; e < NE; e++) { g_off[e] = off; off += g_count[e]; }
    }
}

__global__ void build_kernel() {
    int t = blockIdx.x * blockDim.x + threadIdx.x;
    if (t >= T_TOK) return;
#pragma unroll
    for (int j = 0; j < 2; j++) {
        int e = g_choice[2 * t + j];
        int p = atomicAdd(&g_count2[e], 1);
        int s = g_off[e] + p;
        g_tokOf[s] = t;
        g_wt[s] = g_cw[2 * t + j];
        g_slot[2 * t + j] = s;
    }
}

// gather tokens -> fp16 pairs
__global__ void gather_kernel(const float* __restrict__ x) {
    size_t idx = (size_t)blockIdx.x * blockDim.x + threadIdx.x;
    if (idx >= (size_t)NA * (DIMN / 8)) return;
    int row = (int)(idx / (DIMN / 8));
    int g = (int)(idx % (DIMN / 8)) * 8;
    int tok = g_tokOf[row];
    const float* sp = &x[(size_t)tok * DIMN + g];
    float4 v0 = *reinterpret_cast<const float4*>(sp);
    float4 v1 = *reinterpret_cast<const float4*>(sp + 4);
    uint32_t* dp = &g_Xh[(size_t)row * (DIMN / 2) + g / 2];
    uint4 o;
    o.x = pack_h2(v0.x, v0.y); o.y = pack_h2(v0.z, v0.w);
    o.z = pack_h2(v1.x, v1.y); o.w = pack_h2(v1.z, v1.w);
    *reinterpret_cast<uint4*>(dp) = o;
}

// w1/w3 -> fp16 pairs (natural [e][n][k/2])
__global__ void convw13_kernel(const float* __restrict__ w1, const float* __restrict__ w3) {
    size_t idx = (size_t)blockIdx.x * blockDim.x + threadIdx.x;
    if (idx >= (size_t)NE * HIDN * DIMN / 8) return;
    size_t o = idx * 8;
    {
        float4 v0 = *reinterpret_cast<const float4*>(&w1[o]);
        float4 v1 = *reinterpret_cast<const float4*>(&w1[o + 4]);
        uint4 u;
        u.x = pack_h2(v0.x, v0.y); u.y = pack_h2(v0.z, v0.w);
        u.z = pack_h2(v1.x, v1.y); u.w = pack_h2(v1.z, v1.w);
        *reinterpret_cast<uint4*>(&g_w1h[o / 2]) = u;
    }
    {
        float4 v0 = *reinterpret_cast<const float4*>(&w3[o]);
        float4 v1 = *reinterpret_cast<const float4*>(&w3[o + 4]);
        uint4 u;
        u.x = pack_h2(v0.x, v0.y); u.y = pack_h2(v0.z, v0.w);
        u.z = pack_h2(v1.x, v1.y); u.w = pack_h2(v1.z, v1.w);
        *reinterpret_cast<uint4*>(&g_w3h[o / 2]) = u;
    }
}

// w2 [e][k][n] -> transposed fp16 pairs [e][n][k/2]
__global__ void convw2_kernel(const float* __restrict__ w2) {
    __shared__ float tile[32][17];
    int e = blockIdx.z;
    int n0 = blockIdx.x * 16;
    int k0 = blockIdx.y * 32;
    int tx = threadIdx.x, ty = threadIdx.y;   // 16 x 16
    const float* wp = w2 + (size_t)e * HIDN * DIMN;
#pragma unroll
    for (int i = 0; i < 2; i++)
        tile[ty + 16 * i][tx] = wp[(size_t)(k0 + ty + 16 * i) * DIMN + n0 + tx];
    __syncthreads();
    // out: n = n0+ty, k-pair u32 index = k0/2 + tx
    uint32_t v = pack_h2(tile[2 * tx][ty], tile[2 * tx + 1][ty]);
    g_w2h[((size_t)e * DIMN + n0 + ty) * (HIDN / 2) + k0 / 2 + tx] = v;
}

// ============================ ffn1: H = silu(Xh W1^T) * (Xh W3^T) ============================
// BM=128 BN=64 BK=32(fp16). 256 threads, 8 warps 4(m)x2(n); warp tile 32x32 dual.
__global__ void __launch_bounds__(256, 2) ffn1_kernel() {
    int e = blockIdx.z;
    int cnt = g_count[e];
    int mb = blockIdx.y;
    if (mb * 128 >= cnt) return;
    int base = g_off[e] + mb * 128;
    int n0 = blockIdx.x * 64;

    extern __shared__ uint32_t smem[];
    uint32_t* As  = smem;                        // [NSTG][128*PADU]
    uint32_t* B1s = As  + NSTG * 128 * PADU;     // [NSTG][64*PADU]
    uint32_t* B3s = B1s + NSTG * 64 * PADU;      // [NSTG][64*PADU]
    const int A_STG = 128 * PADU, B_STG = 64 * PADU;

    int tid = threadIdx.x, wid = tid >> 5, lane = tid & 31;
    int wm = wid & 3, wn = wid >> 2;
    int q = lane >> 2, t4 = lane & 3;

    // A loader: row = tid>>1, u32 offset (tid&1)*8 + {0,4}
    int arowL = tid >> 1, apart = tid & 1;
    int arow = base + arowL; if (arow >= NA) arow = NA - 1;
    const uint32_t* srcA0 = g_Xh + (size_t)arow * (DIMN / 2) + apart * 8;
    uint32_t dstA0 = smem_u32(&As[arowL * PADU + apart * 8]);

    // B loader: t<128 -> w1, t>=128 -> w3; row = (t&127)>>1
    int browL = (tid & 127) >> 1, bpart = tid & 1, bmat = tid >> 7;
    const uint32_t* srcB0 = (bmat ? g_w3h : g_w1h)
        + ((size_t)e * HIDN + n0 + browL) * (DIMN / 2) + bpart * 8;
    uint32_t dstB0 = smem_u32((bmat ? B3s : B1s) + browL * PADU + bpart * 8);

    float acc1[2][4][4], acc3[2][4][4];
#pragma unroll
    for (int i = 0; i < 2; i++)
#pragma unroll
        for (int j = 0; j < 4; j++)
#pragma unroll
            for (int v = 0; v < 4; v++) { acc1[i][j][v] = 0.f; acc3[i][j][v] = 0.f; }

    auto issue = [&](int s, int kc) {
        uint32_t aoff = (uint32_t)(s * A_STG * 4);
        uint32_t boff = (uint32_t)(s * B_STG * 4);
        const uint32_t* sa = srcA0 + kc * 16;     // 16 u32 = 32 fp16 per stage
        CP_ASYNC16(dstA0 + aoff, sa); CP_ASYNC16(dstA0 + aoff + 16, sa + 4);
        const uint32_t* sb = srcB0 + kc * 16;
        CP_ASYNC16(dstB0 + boff, sb); CP_ASYNC16(dstB0 + boff + 16, sb + 4);
        CP_COMMIT();
    };

    const int KT = DIMN / BKF;   // 32
    issue(0, 0); issue(1, 1);

    int stg = 0;
    for (int kt = 0; kt < KT; kt++) {
        CP_WAIT(1);
        __syncthreads();
        if (kt + 2 < KT) {
            int s = stg + 2; if (s >= NSTG) s -= NSTG;
            issue(s, kt + 2);
        }

        const uint32_t* A  = As  + stg * A_STG;
        const uint32_t* B1 = B1s + stg * B_STG;
        const uint32_t* B3 = B3s + stg * B_STG;
#pragma unroll
        for (int kk = 0; kk < 2; kk++) {
            int c0 = kk * 8 + t4;
            uint32_t a[2][4];
#pragma unroll
            for (int i = 0; i < 2; i++) {
                int r = wm * 32 + i * 16 + q;
                a[i][0] = A[r * PADU + c0];
                a[i][1] = A[(r + 8) * PADU + c0];
                a[i][2] = A[r * PADU + c0 + 4];
                a[i][3] = A[(r + 8) * PADU + c0 + 4];
            }
            uint32_t b1[4][2], b3[4][2];
#pragma unroll
            for (int j = 0; j < 4; j++) {
                int n = wn * 32 + j * 8 + q;
                b1[j][0] = B1[n * PADU + c0];
                b1[j][1] = B1[n * PADU + c0 + 4];
                b3[j][0] = B3[n * PADU + c0];
                b3[j][1] = B3[n * PADU + c0 + 4];
            }
#pragma unroll
            for (int i = 0; i < 2; i++)
#pragma unroll
                for (int j = 0; j < 4; j++) {
                    mma_f16(acc1[i][j], a[i], b1[j]);
                    mma_f16(acc3[i][j], a[i], b3[j]);
                }
        }
        if (++stg >= NSTG) stg = 0;
    }
    CP_WAIT(0);

    // epilogue: h = silu(z1)*z3, store fp16 pairs
#pragma unroll
    for (int i = 0; i < 2; i++) {
#pragma unroll
        for (int half = 0; half < 2; half++) {
            int rloc = wm * 32 + i * 16 + q + half * 8;
            if (mb * 128 + rloc < cnt) {
                uint32_t* hrow = g_Hh + (size_t)(base + rloc) * (HIDN / 2) + n0 / 2;
#pragma unroll
                for (int j = 0; j < 4; j++) {
                    int cl = wn * 32 + j * 8 + t4 * 2;
                    float z0 = acc1[i][j][half * 2 + 0];
                    float z1 = acc1[i][j][half * 2 + 1];
                    float h0 = z0 / (1.f + __expf(-z0)) * acc3[i][j][half * 2 + 0];
                    float h1 = z1 / (1.f + __expf(-z1)) * acc3[i][j][half * 2 + 1];
                    hrow[cl / 2] = pack_h2(h0, h1);
                }
            }
        }
    }
}

// ============================ ffn2: P = H W2 ============================
// BM=128 BN=128 BK=32(fp16). 256 threads, 8 warps 4(m)x2(n); warp tile 32x64.
__global__ void __launch_bounds__(256, 2) ffn2_kernel() {
    int e = blockIdx.z;
    int cnt = g_count[e];
    int mb = blockIdx.y;
    if (mb * 128 >= cnt) return;
    int base = g_off[e] + mb * 128;
    int n0 = blockIdx.x * 128;

    extern __shared__ uint32_t smem[];
    uint32_t* As = smem;                         // [NSTG][128*PADU]
    uint32_t* Bs = As + NSTG * 128 * PADU;       // [NSTG][128*PADU]
    const int A_STG = 128 * PADU, B_STG = 128 * PADU;

    int tid = threadIdx.x, wid = tid >> 5, lane = tid & 31;
    int wm = wid & 3, wn = wid >> 2;
    int q = lane >> 2, t4 = lane & 3;

    int arowL = tid >> 1, apart = tid & 1;
    int arow = base + arowL; if (arow >= NA) arow = NA - 1;
    const uint32_t* srcA0 = g_Hh + (size_t)arow * (HIDN / 2) + apart * 8;
    uint32_t dstA0 = smem_u32(&As[arowL * PADU + apart * 8]);

    // B loader: transposed w2h rows (n), 128 rows x 16 u32 per stage
    int browL = tid >> 1, bpart = tid & 1;
    const uint32_t* srcB0 = g_w2h + ((size_t)e * DIMN + n0 + browL) * (HIDN / 2) + bpart * 8;
    uint32_t dstB0 = smem_u32(&Bs[browL * PADU + bpart * 8]);

    float acc[2][8][4];
#pragma unroll
    for (int i = 0; i < 2; i++)
#pragma unroll
        for (int j = 0; j < 8; j++)
#pragma unroll
            for (int v = 0; v < 4; v++) acc[i][j][v] = 0.f;

    auto issue = [&](int s, int kc) {
        uint32_t aoff = (uint32_t)(s * A_STG * 4);
        uint32_t boff = (uint32_t)(s * B_STG * 4);
        const uint32_t* sa = srcA0 + kc * 16;
        CP_ASYNC16(dstA0 + aoff, sa); CP_ASYNC16(dstA0 + aoff + 16, sa + 4);
        const uint32_t* sb = srcB0 + kc * 16;
        CP_ASYNC16(dstB0 + boff, sb); CP_ASYNC16(dstB0 + boff + 16, sb + 4);
        CP_COMMIT();
    };

    const int KT = HIDN / BKF;   // 64
    issue(0, 0); issue(1, 1);

    int stg = 0;
    for (int kt = 0; kt < KT; kt++) {
        CP_WAIT(1);
        __syncthreads();
        if (kt + 2 < KT) {
            int s = stg + 2; if (s >= NSTG) s -= NSTG;
            issue(s, kt + 2);
        }

        const uint32_t* A = As + stg * A_STG;
        const uint32_t* B = Bs + stg * B_STG;
#pragma unroll
        for (int kk = 0; kk < 2; kk++) {
            int c0 = kk * 8 + t4;
            uint32_t a[2][4];
#pragma unroll
            for (int i = 0; i < 2; i++) {
                int r = wm * 32 + i * 16 + q;
                a[i][0] = A[r * PADU + c0];
                a[i][1] = A[(r + 8) * PADU + c0];
                a[i][2] = A[r * PADU + c0 + 4];
                a[i][3] = A[(r + 8) * PADU + c0 + 4];
            }
            uint32_t b[8][2];
#pragma unroll
            for (int j = 0; j < 8; j++) {
                int n = wn * 64 + j * 8 + q;
                b[j][0] = B[n * PADU + c0];
                b[j][1] = B[n * PADU + c0 + 4];
            }
#pragma unroll
            for (int i = 0; i < 2; i++)
#pragma unroll
                for (int j = 0; j < 8; j++)
                    mma_f16(acc[i][j], a[i], b[j]);
        }
        if (++stg >= NSTG) stg = 0;
    }
    CP_WAIT(0);

#pragma unroll
    for (int i = 0; i < 2; i++) {
#pragma unroll
        for (int half = 0; half < 2; half++) {
            int rloc = wm * 32 + i * 16 + q + half * 8;
            if (mb * 128 + rloc < cnt) {
                float* prow = g_P + (size_t)(base + rloc) * DIMN + n0;
#pragma unroll
                for (int j = 0; j < 8; j++) {
                    int cl = wn * 64 + j * 8 + t4 * 2;
                    *reinterpret_cast<float2*>(&prow[cl]) =
                        make_float2(acc[i][j][half * 2 + 0], acc[i][j][half * 2 + 1]);
                }
            }
        }
    }
}

// ============================ combine ============================
__global__ void combine_kernel(float* __restrict__ y) {
    size_t idx = (size_t)blockIdx.x * blockDim.x + threadIdx.x;
    if (idx >= (size_t)T_TOK * DIMN / 4) return;
    int t = (int)(idx / (DIMN / 4));
    int d4 = (int)(idx % (DIMN / 4)) * 4;
    int s0 = g_slot[2 * t], s1 = g_slot[2 * t + 1];
    float w0 = g_wt[s0], w1 = g_wt[s1];
    float4 p0 = *reinterpret_cast<const float4*>(&g_P[(size_t)s0 * DIMN + d4]);
    float4 p1 = *reinterpret_cast<const float4*>(&g_P[(size_t)s1 * DIMN + d4]);
    float4 r;
    r.x = w0 * p0.x + w1 * p1.x;
    r.y = w0 * p0.y + w1 * p1.y;
    r.z = w0 * p0.z + w1 * p1.z;
    r.w = w0 * p0.w + w1 * p1.w;
    *reinterpret_cast<float4*>(&y[(size_t)t * DIMN + d4]) = r;
}

// ============================ launch ============================
extern "C" void kernel_launch(void* const* d_in, const int* in_sizes, int n_in,
                              void* d_out, int out_size) {
    const float* x  = (const float*)d_in[0];
    const float* wg = (const float*)d_in[1];
    const float* w1 = (const float*)d_in[2];
    const float* w2 = (const float*)d_in[3];
    const float* w3 = (const float*)d_in[4];
    float* y = (float*)d_out;

    const int smem1 = NSTG * (128 + 64 + 64) * PADU * 4;   // 61440
    const int smem2 = NSTG * (128 + 128) * PADU * 4;       // 61440
    cudaFuncSetAttribute(ffn1_kernel, cudaFuncAttributeMaxDynamicSharedMemorySize, smem1);
    cudaFuncSetAttribute(ffn2_kernel, cudaFuncAttributeMaxDynamicSharedMemorySize, smem2);

    reset_kernel<<<1, 32>>>();
    gate_kernel<<<T_TOK / 8, 256>>>(x, wg);
    scan_kernel<<<1, 32>>>();
    build_kernel<<<T_TOK / 256, 256>>>();
    gather_kernel<<<(int)(((size_t)NA * (DIMN / 8) + 255) / 256), 256>>>(x);
    convw13_kernel<<<(int)(((size_t)NE * HIDN * DIMN / 8 + 255) / 256), 256>>>(w1, w3);
    convw2_kernel<<<dim3(DIMN / 16, HIDN / 32, NE), dim3(16, 16)>>>(w2);
    ffn1_kernel<<<dim3(HIDN / 64, 128, NE), 256, smem1>>>();
    ffn2_kernel<<<dim3(DIMN / 128, 128, NE), 256, smem2>>>();
    combine_kernel<<<(T_TOK * DIMN / 4 + 255) / 256, 256>>>(y);
}